// round 13
// baseline (speedup 1.0000x reference)
#include <cuda_runtime.h>

// LbpBlock: out = concat([x, pad(x_cat)], ch axis)
//   y[n,o,h,w] = sum_c x[n,c,h,w]*conv_w[o,c]   (c=3, o=64)
//   x_cat interior = sum_l H(y_c - y_shift_l) * exp(w[o,l]), zero border.
// x: (8,3,256,256) f32, conv_w: (64,3), w: (64,8) -> out: (8,67,256,256)
//
// R13 = R12 engine with cg=16 channel split (4 ch = ONE chunk per block):
// sy single-buffer 40.3KB -> 4 CTAs/SM = 32 warps (2x occupancy) at the
// same 128-reg budget. One barrier per block. 4096 blocks, ~7 waves.

#define NN   8
#define CIN  3
#define HH   256
#define WW   256
#define TH   32
#define TW   64
#define NT   256
#define HALO_H 34
#define HALO_W 66
#define CP   74                    // swizzled f4 row pitch (sw(65)=73)
#define PLANE (HH * WW)
#define NF4  544                   // interior f4 slots: 34 rows x 16
#define NSLOT (NF4 + 68)           // + scalar edge slots (34 rows x 2)

struct Sm {
    float4 sy[HALO_H][CP];         // 40256 B: y for this block's 4 channels
    float2 sewp[2][8];             // exp(w) for the 2 channel pairs
};                                  // 40384 B -> 4 CTAs/SM (161.5 KB)

__device__ __forceinline__ int sw(int c) { return c + (c >> 3); }

__global__ __launch_bounds__(NT, 4)
void lbp_main(const float* __restrict__ x,
              const float* __restrict__ cw,
              const float* __restrict__ w,
              float* __restrict__ out)
{
    extern __shared__ unsigned char raw[];
    Sm* sm = (Sm*)raw;

    const int tid = threadIdx.x;
    const int bz  = blockIdx.z;
    const int n   = bz >> 4;          // image
    const int cg  = bz & 15;          // channel group (4 ch = 1 chunk)
    const int o0  = 4 * cg;
    const int h0  = blockIdx.y * TH;
    const int w0  = blockIdx.x * TW;

    // ---- exp(w) for this block's 2 channel pairs (16 expf total) ----
    if (tid < 16) {
        const int pi = tid >> 3, l = tid & 7;
        sm->sewp[pi][l] = make_float2(__expf(w[(o0 + 2 * pi) * 8 + l]),
                                      __expf(w[(o0 + 2 * pi + 1) * 8 + l]));
    }

    // ---- conv weights: 3 broadcast LDG.128 (12*cg % 4 == 0 -> aligned) ----
    const float4* cw4 = (const float4*)(cw + 3 * o0);
    const float4 W0 = cw4[0], W1 = cw4[1], W2 = cw4[2];
    // per-channel weights: ch0=(W0.x,W0.y,W0.z) ch1=(W0.w,W1.x,W1.y)
    //                      ch2=(W1.z,W1.w,W2.x) ch3=(W2.y,W2.z,W2.w)

    // ---- x halo -> registers, shift-only indexing ----
    // slot s < NF4: interior f4 (row r = s>>4, 4 px at halo col 1+4q)
    // slot s >= NF4: scalar edge (row (s-NF4)>>1, col 0 or 65)
    float xs[3][3][4];                // [k][plane][px]
    int   rk[3], ck[3], tk[3];        // row, first halo col, type(0=f4,1=sc,2=none)
    #pragma unroll
    for (int k = 0; k < 3; k++) {
        const int s = tid + k * NT;
        #pragma unroll
        for (int p = 0; p < 3; p++)
            #pragma unroll
            for (int i = 0; i < 4; i++)
                xs[k][p][i] = 0.f;
        if (s < NF4) {
            const int r = s >> 4, q = s & 15;
            rk[k] = r; ck[k] = 1 + 4 * q; tk[k] = 0;
            const int gh = h0 - 1 + r;
            if ((unsigned)gh < HH) {
                const int base = (n * CIN * HH + gh) * WW + (w0 + 4 * q);
                #pragma unroll
                for (int p = 0; p < 3; p++) {
                    const float4 t = *(const float4*)(x + base + p * PLANE);
                    xs[k][p][0] = t.x; xs[k][p][1] = t.y;
                    xs[k][p][2] = t.z; xs[k][p][3] = t.w;
                }
            }
        } else if (s < NSLOT) {
            const int e2 = s - NF4;
            const int r = e2 >> 1, side = e2 & 1;
            rk[k] = r; ck[k] = side ? 65 : 0; tk[k] = 1;
            const int gh = h0 - 1 + r;
            const int gw = w0 - 1 + ck[k];
            if ((unsigned)gh < HH && (unsigned)gw < WW) {
                const int base = (n * CIN * HH + gh) * WW + gw;
                #pragma unroll
                for (int p = 0; p < 3; p++)
                    xs[k][p][0] = x[base + p * PLANE];
            }
        } else {
            rk[k] = 0; ck[k] = 0; tk[k] = 2;
        }
    }

    // ---- distributed copy: every block copies 96 f4 of its tile ----
    if (tid < 96) {
        const float4* x4 = (const float4*)(x + n * CIN * PLANE);
        float4*       o4 = (float4*)(out + n * 67 * PLANE);
        const int f   = cg * 96 + tid;       // 1536 f4 per tile / 16 groups
        const int c   = f >> 9;
        const int rem = f & 511;
        const int rr  = rem >> 4;
        const int cc  = rem & 15;
        const int idx = c * (PLANE / 4) + (h0 + rr) * (WW / 4) + (w0 >> 2) + cc;
        o4[idx] = x4[idx];
    }

    // ---- fill this chunk's y (register FMA -> STS.128) ----
    #pragma unroll
    for (int k = 0; k < 3; k++) {
        if (tk[k] == 0) {
            #pragma unroll
            for (int i = 0; i < 4; i++) {
                const float a = xs[k][0][i], b = xs[k][1][i], d = xs[k][2][i];
                float4 v;
                v.x = fmaf(d, W0.z, fmaf(b, W0.y, a * W0.x));
                v.y = fmaf(d, W1.y, fmaf(b, W1.x, a * W0.w));
                v.z = fmaf(d, W2.x, fmaf(b, W1.w, a * W1.z));
                v.w = fmaf(d, W2.w, fmaf(b, W2.z, a * W2.y));
                sm->sy[rk[k]][sw(ck[k] + i)] = v;
            }
        } else if (tk[k] == 1) {
            const float a = xs[k][0][0], b = xs[k][1][0], d = xs[k][2][0];
            float4 v;
            v.x = fmaf(d, W0.z, fmaf(b, W0.y, a * W0.x));
            v.y = fmaf(d, W1.y, fmaf(b, W1.x, a * W0.w));
            v.z = fmaf(d, W2.x, fmaf(b, W1.w, a * W1.z));
            v.w = fmaf(d, W2.w, fmaf(b, W2.z, a * W2.y));
            sm->sy[rk[k]][sw(ck[k])] = v;
        }
    }
    __syncthreads();   // the ONLY barrier

    // ---- phase 2: 2 rows x 4 cols micro-tile, f4 shared window ----
    const int mc  = tid & 15;            // col group (4 px)
    const int mrg = tid >> 4;            // row pair (0..15)
    const int hr0 = 2 * mrg;             // top window halo row
    const int sc0 = 4 * mc;              // window halo col base
    const int oh0 = h0 + 2 * mrg;
    const int owb = w0 + 4 * mc;

    float mk[2][4];
    #pragma unroll
    for (int pr = 0; pr < 2; pr++) {
        const bool hv = ((unsigned)(oh0 + pr - 1) < (unsigned)(HH - 2));
        #pragma unroll
        for (int jj = 0; jj < 4; jj++)
            mk[pr][jj] = (hv && ((unsigned)(owb + jj - 1) < (unsigned)(WW - 2)))
                       ? 1.f : 0.f;
    }
    float* const outB = out + (n * 67 + 3 + o0) * PLANE + owb;

    #define DOPAIR(T, M, Bo, pr, FX, FY, pairI, cA) {                     \
        float2 e[8];                                                      \
        {                                                                 \
            const float4* q4 = (const float4*)&sm->sewp[pairI][0];        \
            _Pragma("unroll")                                             \
            for (int qq = 0; qq < 4; qq++) {                              \
                const float4 u = q4[qq];                                  \
                e[2 * qq]     = make_float2(u.x, u.y);                    \
                e[2 * qq + 1] = make_float2(u.z, u.w);                    \
            }                                                             \
        }                                                                 \
        float rA[4], rB[4];                                               \
        _Pragma("unroll")                                                 \
        for (int jj = 0; jj < 4; jj++) {                                  \
            const float4 ce = M[jj + 1];                                  \
            float a0 = 0.f, a1 = 0.f;                                     \
            /* TL, T, TR, L, BL, B, BR, R (reference shift order) */      \
            if (ce.FX > T[jj     ].FX) a0 += e[0].x;                      \
            if (ce.FY > T[jj     ].FY) a1 += e[0].y;                      \
            if (ce.FX > T[jj + 1 ].FX) a0 += e[1].x;                      \
            if (ce.FY > T[jj + 1 ].FY) a1 += e[1].y;                      \
            if (ce.FX > T[jj + 2 ].FX) a0 += e[2].x;                      \
            if (ce.FY > T[jj + 2 ].FY) a1 += e[2].y;                      \
            if (ce.FX > M[jj     ].FX) a0 += e[3].x;                      \
            if (ce.FY > M[jj     ].FY) a1 += e[3].y;                      \
            if (ce.FX > Bo[jj    ].FX) a0 += e[4].x;                      \
            if (ce.FY > Bo[jj    ].FY) a1 += e[4].y;                      \
            if (ce.FX > Bo[jj + 1].FX) a0 += e[5].x;                      \
            if (ce.FY > Bo[jj + 1].FY) a1 += e[5].y;                      \
            if (ce.FX > Bo[jj + 2].FX) a0 += e[6].x;                      \
            if (ce.FY > Bo[jj + 2].FY) a1 += e[6].y;                      \
            if (ce.FX > M[jj + 2 ].FX) a0 += e[7].x;                      \
            if (ce.FY > M[jj + 2 ].FY) a1 += e[7].y;                      \
            rA[jj] = a0 * mk[pr][jj];                                     \
            rB[jj] = a1 * mk[pr][jj];                                     \
        }                                                                 \
        float* op = outB + (cA) * PLANE + (oh0 + (pr)) * WW;              \
        *(float4*)op           = make_float4(rA[0], rA[1], rA[2], rA[3]); \
        *(float4*)(op + PLANE) = make_float4(rB[0], rB[1], rB[2], rB[3]); \
    }

    {
        // window rows hr0..hr0+2 (18 LDS.128, serves both channel pairs)
        float4 A[6], B[6], C[6];
        #pragma unroll
        for (int j = 0; j < 6; j++) {
            A[j] = sm->sy[hr0    ][sw(sc0 + j)];
            B[j] = sm->sy[hr0 + 1][sw(sc0 + j)];
            C[j] = sm->sy[hr0 + 2][sw(sc0 + j)];
        }

        // pixel row 0: T=A, M=B, Bo=C
        DOPAIR(A, B, C, 0, x, y, 0, 0)
        DOPAIR(A, B, C, 0, z, w, 1, 2)

        // roll: row hr0+3 replaces A
        #pragma unroll
        for (int j = 0; j < 6; j++)
            A[j] = sm->sy[hr0 + 3][sw(sc0 + j)];

        // pixel row 1: T=B, M=C, Bo=A(new)
        DOPAIR(B, C, A, 1, x, y, 0, 0)
        DOPAIR(B, C, A, 1, z, w, 1, 2)
    }
    #undef DOPAIR
}

extern "C" void kernel_launch(void* const* d_in, const int* in_sizes, int n_in,
                              void* d_out, int out_size)
{
    const float* x  = (const float*)d_in[0];
    const float* cw = (const float*)d_in[1];
    const float* w  = (const float*)d_in[2];
    float* out = (float*)d_out;

    const int smbytes = (int)sizeof(Sm);   // 40384
    cudaFuncSetAttribute(lbp_main, cudaFuncAttributeMaxDynamicSharedMemorySize,
                         smbytes);

    dim3 grid(WW / TW, HH / TH, NN * 16);   // (4, 8, 128) = 4096 blocks
    lbp_main<<<grid, NT, smbytes>>>(x, cw, w, out);
}

// round 14
// speedup vs baseline: 1.9895x; 1.9895x over previous
#include <cuda_runtime.h>

// LbpBlock: out = concat([x, pad(x_cat)], ch axis)
//   y[n,o,h,w] = sum_c x[n,c,h,w]*conv_w[o,c]   (c=3, o=64)
//   x_cat interior = sum_l H(y_c - y_shift_l) * exp(w[o,l]), zero border.
// x: (8,3,256,256) f32, conv_w: (64,3), w: (64,8) -> out: (8,67,256,256)
//
// R14: regfile-exact config. 128-thread CTAs, 4 CTAs/SM x 128 regs = the
// full 64K-reg file, 16 warps (structural max for ~120 live regs).
// 4x4 px micro-tile (64x32 tile, cg=16 -> one 4-ch chunk per block):
// window LDS 36 per 64 px-ch (-25% vs 2x4). One barrier per block.

#define NN   8
#define CIN  3
#define HH   256
#define WW   256
#define TH   64                    // tile rows
#define TW   32                    // tile cols
#define NT   128
#define HALO_H 66
#define HALO_W 34
#define CP   38                    // swizzled f4 row pitch (sw(33)=37)
#define PLANE (HH * WW)
#define NF4  528                   // interior f4 slots: 66 rows x 8
#define NSLOT (NF4 + 132)          // + scalar edge slots (66 rows x 2)

struct Sm {
    float4 sy[HALO_H][CP];         // 40128 B: y for this block's 4 channels
    float2 sewp[2][8];             // exp(w) for the 2 channel pairs
};                                  // 40256 B -> 4 CTAs/SM (161 KB)

__device__ __forceinline__ int sw(int c) { return c + (c >> 3); }

__global__ __launch_bounds__(NT, 4)
void lbp_main(const float* __restrict__ x,
              const float* __restrict__ cw,
              const float* __restrict__ w,
              float* __restrict__ out)
{
    extern __shared__ unsigned char raw[];
    Sm* sm = (Sm*)raw;

    const int tid = threadIdx.x;
    const int bz  = blockIdx.z;
    const int n   = bz >> 4;          // image
    const int cg  = bz & 15;          // channel group (4 ch = 1 chunk)
    const int o0  = 4 * cg;
    const int h0  = blockIdx.y * TH;
    const int w0  = blockIdx.x * TW;

    // ---- exp(w) for this block's 2 channel pairs (16 expf total) ----
    if (tid < 16) {
        const int pi = tid >> 3, l = tid & 7;
        sm->sewp[pi][l] = make_float2(__expf(w[(o0 + 2 * pi) * 8 + l]),
                                      __expf(w[(o0 + 2 * pi + 1) * 8 + l]));
    }

    // ---- conv weights: 3 broadcast LDG.128 (12*cg % 4 == 0 -> aligned) ----
    const float4* cw4 = (const float4*)(cw + 3 * o0);
    const float4 W0 = cw4[0], W1 = cw4[1], W2 = cw4[2];
    // ch0=(W0.x,W0.y,W0.z) ch1=(W0.w,W1.x,W1.y)
    // ch2=(W1.z,W1.w,W2.x) ch3=(W2.y,W2.z,W2.w)

    // ---- x halo -> registers, shift-only indexing ----
    // slot s < NF4: interior f4 (row r = s>>3, 4 px at halo col 1+4q)
    // slot s >= NF4: scalar edge (row (s-NF4)>>1, halo col 0 or 33)
    float xs[6][3][4];                // [k][plane][px]; dies after the fill
    int   rk[6], ck[6], tk[6];        // row, first halo col, type(0=f4,1=sc,2=-)
    #pragma unroll
    for (int k = 0; k < 6; k++) {
        const int s = tid + k * NT;
        #pragma unroll
        for (int p = 0; p < 3; p++)
            #pragma unroll
            for (int i = 0; i < 4; i++)
                xs[k][p][i] = 0.f;
        if (s < NF4) {                      // k<4 always here (512 < 528)
            const int r = s >> 3, q = s & 7;
            rk[k] = r; ck[k] = 1 + 4 * q; tk[k] = 0;
            const int gh = h0 - 1 + r;
            if ((unsigned)gh < HH) {
                const int base = (n * CIN * HH + gh) * WW + (w0 + 4 * q);
                #pragma unroll
                for (int p = 0; p < 3; p++) {
                    const float4 t = *(const float4*)(x + base + p * PLANE);
                    xs[k][p][0] = t.x; xs[k][p][1] = t.y;
                    xs[k][p][2] = t.z; xs[k][p][3] = t.w;
                }
            }
        } else if (s < NSLOT) {
            const int e2 = s - NF4;
            const int r = e2 >> 1, side = e2 & 1;
            rk[k] = r; ck[k] = side ? 33 : 0; tk[k] = 1;
            const int gh = h0 - 1 + r;
            const int gw = w0 - 1 + (side ? 33 : 0);
            if ((unsigned)gh < HH && (unsigned)gw < WW) {
                const int base = (n * CIN * HH + gh) * WW + gw;
                #pragma unroll
                for (int p = 0; p < 3; p++)
                    xs[k][p][0] = x[base + p * PLANE];
            }
        } else {
            rk[k] = 0; ck[k] = 0; tk[k] = 2;
        }
    }

    // ---- distributed copy: every block copies 96 f4 of its tile ----
    if (tid < 96) {
        const float4* x4 = (const float4*)(x + n * CIN * PLANE);
        float4*       o4 = (float4*)(out + n * 67 * PLANE);
        const int f   = cg * 96 + tid;       // 1536 f4 per tile / 16 groups
        const int c   = f >> 9;              // 512 f4 per channel-tile
        const int rem = f & 511;
        const int rr  = rem >> 3;            // 64 rows x 8 f4
        const int cc  = rem & 7;
        const int idx = c * (PLANE / 4) + (h0 + rr) * (WW / 4) + (w0 >> 2) + cc;
        o4[idx] = x4[idx];
    }

    // ---- fill this chunk's y (register FMA -> STS.128) ----
    #pragma unroll
    for (int k = 0; k < 6; k++) {
        if (tk[k] == 0) {
            #pragma unroll
            for (int i = 0; i < 4; i++) {
                const float a = xs[k][0][i], b = xs[k][1][i], d = xs[k][2][i];
                float4 v;
                v.x = fmaf(d, W0.z, fmaf(b, W0.y, a * W0.x));
                v.y = fmaf(d, W1.y, fmaf(b, W1.x, a * W0.w));
                v.z = fmaf(d, W2.x, fmaf(b, W1.w, a * W1.z));
                v.w = fmaf(d, W2.w, fmaf(b, W2.z, a * W2.y));
                sm->sy[rk[k]][sw(ck[k] + i)] = v;
            }
        } else if (tk[k] == 1) {
            const float a = xs[k][0][0], b = xs[k][1][0], d = xs[k][2][0];
            float4 v;
            v.x = fmaf(d, W0.z, fmaf(b, W0.y, a * W0.x));
            v.y = fmaf(d, W1.y, fmaf(b, W1.x, a * W0.w));
            v.z = fmaf(d, W2.x, fmaf(b, W1.w, a * W1.z));
            v.w = fmaf(d, W2.w, fmaf(b, W2.z, a * W2.y));
            sm->sy[rk[k]][sw(ck[k])] = v;
        }
    }
    __syncthreads();   // the ONLY barrier (4-warp convoy)

    // ---- phase 2: 4 rows x 4 cols micro-tile, f4 shared rolling window ----
    const int mc  = tid & 7;             // col group (4 px); 8 groups x 4 = 32
    const int mrg = tid >> 3;            // row quad (0..15); 16 x 4 = 64 rows
    const int hr0 = 4 * mrg;             // top window halo row
    const int sc0 = 4 * mc;              // window halo col base
    const int oh0 = h0 + 4 * mrg;
    const int owb = w0 + 4 * mc;

    // border masks: row x col separable
    float rm[4], cm[4];
    #pragma unroll
    for (int pr = 0; pr < 4; pr++)
        rm[pr] = ((unsigned)(oh0 + pr - 1) < (unsigned)(HH - 2)) ? 1.f : 0.f;
    #pragma unroll
    for (int jj = 0; jj < 4; jj++)
        cm[jj] = ((unsigned)(owb + jj - 1) < (unsigned)(WW - 2)) ? 1.f : 0.f;

    float* const outB = out + (n * 67 + 3 + o0) * PLANE + owb;

    // DOPAIR: one pixel row (pr), one channel pair (f4 fields FX/FY).
    #define DOPAIR(T, M, Bo, pr, FX, FY, pairI, cA) {                     \
        float2 e[8];                                                      \
        {                                                                 \
            const float4* q4 = (const float4*)&sm->sewp[pairI][0];        \
            _Pragma("unroll")                                             \
            for (int qq = 0; qq < 4; qq++) {                              \
                const float4 u = q4[qq];                                  \
                e[2 * qq]     = make_float2(u.x, u.y);                    \
                e[2 * qq + 1] = make_float2(u.z, u.w);                    \
            }                                                             \
        }                                                                 \
        float rA[4], rB[4];                                               \
        _Pragma("unroll")                                                 \
        for (int jj = 0; jj < 4; jj++) {                                  \
            const float4 ce = M[jj + 1];                                  \
            float a0 = 0.f, a1 = 0.f;                                     \
            /* TL, T, TR, L, BL, B, BR, R (reference shift order) */      \
            if (ce.FX > T[jj     ].FX) a0 += e[0].x;                      \
            if (ce.FY > T[jj     ].FY) a1 += e[0].y;                      \
            if (ce.FX > T[jj + 1 ].FX) a0 += e[1].x;                      \
            if (ce.FY > T[jj + 1 ].FY) a1 += e[1].y;                      \
            if (ce.FX > T[jj + 2 ].FX) a0 += e[2].x;                      \
            if (ce.FY > T[jj + 2 ].FY) a1 += e[2].y;                      \
            if (ce.FX > M[jj     ].FX) a0 += e[3].x;                      \
            if (ce.FY > M[jj     ].FY) a1 += e[3].y;                      \
            if (ce.FX > Bo[jj    ].FX) a0 += e[4].x;                      \
            if (ce.FY > Bo[jj    ].FY) a1 += e[4].y;                      \
            if (ce.FX > Bo[jj + 1].FX) a0 += e[5].x;                      \
            if (ce.FY > Bo[jj + 1].FY) a1 += e[5].y;                      \
            if (ce.FX > Bo[jj + 2].FX) a0 += e[6].x;                      \
            if (ce.FY > Bo[jj + 2].FY) a1 += e[6].y;                      \
            if (ce.FX > M[jj + 2 ].FX) a0 += e[7].x;                      \
            if (ce.FY > M[jj + 2 ].FY) a1 += e[7].y;                      \
            const float m = rm[pr] * cm[jj];                              \
            rA[jj] = a0 * m;                                              \
            rB[jj] = a1 * m;                                              \
        }                                                                 \
        float* op = outB + (cA) * PLANE + (oh0 + (pr)) * WW;              \
        *(float4*)op           = make_float4(rA[0], rA[1], rA[2], rA[3]); \
        *(float4*)(op + PLANE) = make_float4(rB[0], rB[1], rB[2], rB[3]); \
    }

    #define LOADROW(D, r) {                        \
        _Pragma("unroll")                          \
        for (int j = 0; j < 6; j++)                \
            D[j] = sm->sy[r][sw(sc0 + j)];         \
    }

    {
        float4 A[6], B[6], C[6];
        LOADROW(A, hr0)
        LOADROW(B, hr0 + 1)
        LOADROW(C, hr0 + 2)

        // pixel row 0: T=A, M=B, Bo=C
        DOPAIR(A, B, C, 0, x, y, 0, 0)
        DOPAIR(A, B, C, 0, z, w, 1, 2)

        LOADROW(A, hr0 + 3)
        // pixel row 1: T=B, M=C, Bo=A
        DOPAIR(B, C, A, 1, x, y, 0, 0)
        DOPAIR(B, C, A, 1, z, w, 1, 2)

        LOADROW(B, hr0 + 4)
        // pixel row 2: T=C, M=A, Bo=B
        DOPAIR(C, A, B, 2, x, y, 0, 0)
        DOPAIR(C, A, B, 2, z, w, 1, 2)

        LOADROW(C, hr0 + 5)
        // pixel row 3: T=A, M=B, Bo=C
        DOPAIR(A, B, C, 3, x, y, 0, 0)
        DOPAIR(A, B, C, 3, z, w, 1, 2)
    }
    #undef DOPAIR
    #undef LOADROW
}

extern "C" void kernel_launch(void* const* d_in, const int* in_sizes, int n_in,
                              void* d_out, int out_size)
{
    const float* x  = (const float*)d_in[0];
    const float* cw = (const float*)d_in[1];
    const float* w  = (const float*)d_in[2];
    float* out = (float*)d_out;

    const int smbytes = (int)sizeof(Sm);   // 40256
    cudaFuncSetAttribute(lbp_main, cudaFuncAttributeMaxDynamicSharedMemorySize,
                         smbytes);

    dim3 grid(WW / TW, HH / TH, NN * 16);   // (8, 4, 128) = 4096 blocks
    lbp_main<<<grid, NT, smbytes>>>(x, cw, w, out);
}